// round 17
// baseline (speedup 1.0000x reference)
#include <cuda_runtime.h>
#include <math.h>

// Shapes (fixed by the problem)
#define BB 128
#define NN 500
#define CC 80
// Head index used = 5 (last of 6)

// d_out layout (float32, 320000 elems):
//   [0      : 128000) boxes_next (B,N,2)
//   [128000 : 192000) scores     (B,N)
//   [192000 : 256000) labels     (B,N) as float
//   [256000 : 320000) nms_keep   (B,N) as 0/1 float
#define OFF_SCORES 128000
#define OFF_LABELS 192000
#define OFF_KEEP   256000

// Cross-block handshake state (zero-initialized at module load; the last
// departing block resets both counters every launch -> graph-replay safe).
__device__ unsigned g_arrive;
__device__ unsigned g_depart;
__device__ int      g_keep_arr[NN];

// ---------------------------------------------------------------------------
// ONE fused kernel: one block of 1024 threads (32 warps) per batch.
//  - S phase (2 pipelined passes, 4 lanes/row): softmax score + argmax label.
//    Block 0's S phase ALSO yields the batch-0 keep mask for free
//    (keep = max over all 80 logits > 0 = the softmax max test), published
//    through g_keep_arr + an arrive counter. No block re-reads batch 0.
//  - NMS tail (label-bucketed rank-sort + 64-bit masks + bitmask greedy)
//    runs BEFORE the spin-wait, hiding all handshake latency.
//  - Final box update reads g_keep_arr after the (already-satisfied) spin.
// All 128 blocks are co-resident (<=148 SMs, one wave) -> spin is safe.
// ---------------------------------------------------------------------------
__global__ __launch_bounds__(1024)
void fused_kernel(const float* __restrict__ boxes_t,
                  const float* __restrict__ pc,
                  const float* __restrict__ pb,
                  const float* __restrict__ noise,
                  const float* __restrict__ fresh,
                  const float* __restrict__ ac,
                  const int*   __restrict__ t_now_p,
                  const int*   __restrict__ t_next_p,
                  float* __restrict__ out)
{
    const int b      = blockIdx.x;
    const int tid    = threadIdx.x;
    const int q      = tid & 3;   // quarter of a row
    const int slot_b = tid >> 2;  // row-slot 0..255 per pass

    __shared__ unsigned sukey[NN];            // ~bits(score) per row
    __shared__ int      slabel[NN];           // argmax label per row
    __shared__ unsigned long long gkey[NN];   // keys in grouped (unsorted) order
    __shared__ float ss1[NN], ss2[NN], ssw[NN];  // coords in sorted order
    __shared__ unsigned long long smask[NN];  // per sorted slot: mask / flag
    __shared__ unsigned long long gsup[CC];
    __shared__ int hist[CC], offs[CC], cur[CC];

    if (tid < CC) hist[tid] = 0;

    // ---- early independent loads: box-update operands ----
    float2 bt, bs, nz, fz;
    if (tid < NN) {
        const size_t idx = (size_t)b * NN + tid;
        bt = ((const float2*)boxes_t)[idx];
        bs = ((const float2*)(pb + (size_t)5 * BB * NN * 2))[idx];
        nz = ((const float2*)noise)[idx];
        fz = ((const float2*)fresh)[idx];
    }
    const int   t_now      = *t_now_p;
    const int   t_next     = *t_next_p;
    const float alpha      = ac[t_now];
    const float alpha_next = ac[t_next];

    const float* pc5 = pc + (size_t)5 * BB * NN * CC;

    // ---- pipelined score phases (2 passes of 256 rows), own batch only ----
    float4 sA[5], sB[5];
    {
        int slot  = slot_b;
        int slotc = slot < NN ? slot : NN - 1;
        const float4* rp = (const float4*)(pc5 + ((size_t)b * NN + slotc) * CC);
        #pragma unroll
        for (int i = 0; i < 5; ++i) sA[i] = __ldg(rp + q + 4 * i);
    }

    #pragma unroll
    for (int p = 0; p < 2; ++p) {
        float4* curb = (p & 1) ? sB : sA;
        float4* nxtb = (p & 1) ? sA : sB;

        if (p < 1) {
            int slot  = (p + 1) * 256 + slot_b;
            int slotc = slot < NN ? slot : NN - 1;
            const float4* rp = (const float4*)(pc5 + ((size_t)b * NN + slotc) * CC);
            #pragma unroll
            for (int i = 0; i < 5; ++i) nxtb[i] = __ldg(rp + q + 4 * i);
        }

        const int slot = p * 256 + slot_b;

        {
            float4 a0 = curb[0], a1 = curb[1], a2 = curb[2], a3 = curb[3], a4 = curb[4];

            float lmax = fmaxf(fmaxf(fmaxf(a0.x, a0.y), fmaxf(a0.z, a0.w)),
                         fmaxf(fmaxf(fmaxf(a1.x, a1.y), fmaxf(a1.z, a1.w)),
                         fmaxf(fmaxf(fmaxf(a2.x, a2.y), fmaxf(a2.z, a2.w)),
                         fmaxf(fmaxf(fmaxf(a3.x, a3.y), fmaxf(a3.z, a3.w)),
                         fmaxf(fmaxf(a4.x, a4.y), fmaxf(a4.z, a4.w))))));

            // local argmax over first 79 (exclude col 79 = q==3 lane's a4.w).
            float v; int ai;
            const int c0 = 4 * q;
            v = a0.x; ai = c0;
#define ARGM(val, col) if ((val) > v) { v = (val); ai = (col); }
            ARGM(a0.y, c0 + 1) ARGM(a0.z, c0 + 2) ARGM(a0.w, c0 + 3)
            ARGM(a1.x, c0 + 16) ARGM(a1.y, c0 + 17) ARGM(a1.z, c0 + 18) ARGM(a1.w, c0 + 19)
            ARGM(a2.x, c0 + 32) ARGM(a2.y, c0 + 33) ARGM(a2.z, c0 + 34) ARGM(a2.w, c0 + 35)
            ARGM(a3.x, c0 + 48) ARGM(a3.y, c0 + 49) ARGM(a3.z, c0 + 50) ARGM(a3.w, c0 + 51)
            ARGM(a4.x, c0 + 64) ARGM(a4.y, c0 + 65) ARGM(a4.z, c0 + 66)
            if (q != 3) ARGM(a4.w, c0 + 67)
#undef ARGM

            float m = lmax;
            m = fmaxf(m, __shfl_xor_sync(0xffffffffu, m, 1));
            m = fmaxf(m, __shfl_xor_sync(0xffffffffu, m, 2));

            #pragma unroll
            for (int o = 1; o <= 2; o <<= 1) {
                float ov = __shfl_xor_sync(0xffffffffu, v, o);
                int   oi = __shfl_xor_sync(0xffffffffu, ai, o);
                if (ov > v || (ov == v && oi < ai)) { v = ov; ai = oi; }
            }

            float s = __expf(a0.x - m) + __expf(a0.y - m) + __expf(a0.z - m) + __expf(a0.w - m)
                    + __expf(a1.x - m) + __expf(a1.y - m) + __expf(a1.z - m) + __expf(a1.w - m)
                    + __expf(a2.x - m) + __expf(a2.y - m) + __expf(a2.z - m) + __expf(a2.w - m)
                    + __expf(a3.x - m) + __expf(a3.y - m) + __expf(a3.z - m) + __expf(a3.w - m)
                    + __expf(a4.x - m) + __expf(a4.y - m) + __expf(a4.z - m) + __expf(a4.w - m);
            s += __shfl_xor_sync(0xffffffffu, s, 1);
            s += __shfl_xor_sync(0xffffffffu, s, 2);

            if (q == 0 && slot < NN) {
                float sc = __expf(v - m) / s;
                out[OFF_SCORES + (size_t)b * NN + slot] = sc;
                out[OFF_LABELS + (size_t)b * NN + slot] = (float)ai;
                sukey[slot]  = ~__float_as_uint(sc);  // scores > 0: order-preserving
                slabel[slot] = ai;
                // batch 0: m IS the keep test (max sigmoid > 0.5 <=> max logit > 0)
                if (b == 0) g_keep_arr[slot] = (m > 0.0f);
            }
        }
    }

    // publish: writers fence their global stores, block barrier, then arrive
    if (b == 0) __threadfence();
    __syncthreads();   // also makes sukey/slabel/hist=0 visible block-wide
    if (tid == 0) atomicAdd(&g_arrive, 1u);

    // DDIM scalars (same fp32 op sequence as reference)
    const float sqrt_recip   = sqrtf(1.0f / alpha);
    const float sqrt_recipm1 = sqrtf(1.0f / alpha - 1.0f);
    const float sigma = sqrtf((1.0f - alpha / alpha_next) * (1.0f - alpha_next)
                              / (1.0f - alpha));
    const float ccoef = sqrtf(1.0f - alpha_next - sigma * sigma);
    const float sq_an = sqrtf(alpha_next);

    // ---- NMS staging (no keep needed) ----
    float x1 = 0.0f, x2 = 0.0f, w = 0.0f;
    unsigned long long key = 0ull;
    int g = 0;
    if (tid < NN) {
        w  = fmaxf(bs.y, 0.0001f);
        x1 = bs.x - w * 0.5f;
        x2 = bs.x + w * 0.5f;
        key = ((unsigned long long)sukey[tid] << 32) | (unsigned)tid; // asc == (score desc, idx asc)
        g   = slabel[tid];
        atomicAdd(&hist[g], 1);
    }
    __syncthreads();

    // ---- prefix sum over 80 label bins: parallel per-thread ----
    if (tid < CC) {
        int acc = 0;
        for (int l = 0; l < tid; ++l) acc += hist[l];
        offs[tid] = acc;
        cur[tid]  = acc;
    }
    __syncthreads();

    // ---- scatter keys into grouped order ----
    if (tid < NN) {
        int pos = atomicAdd(&cur[g], 1);
        gkey[pos] = key;
    }
    __syncthreads();

    // ---- rank via sequential scan; sorted coord arrays from registers ----
    int base0 = 0, k = 0, r = 0;
    if (tid < NN) {
        base0 = offs[g];
        k     = hist[g];
        for (int i = 0; i < k; ++i)
            r += (gkey[base0 + i] < key);
        ss1[base0 + r] = x1;
        ss2[base0 + r] = x2;
        ssw[base0 + r] = w;
    }
    __syncthreads();

    // ---- suppression masks (sequential-address LDS, no indirection) ----
    if (tid < NN && k <= 64) {
        unsigned long long m = 0ull;
        for (int qq = r + 1; qq < k; ++qq) {
            float inter = fmaxf(0.0f, fminf(x2, ss2[base0 + qq])
                                    - fmaxf(x1, ss1[base0 + qq]));
            float uni   = w + ssw[base0 + qq] - inter;
            if (inter / fmaxf(uni, 1e-9f) > 0.5f) m |= (1ull << qq);
        }
        smask[base0 + r] = m;
    }
    __syncthreads();

    // ---- greedy: thread per group ----
    if (tid < CC) {
        int kk = hist[tid], bb0 = offs[tid];
        unsigned long long sup = 0ull;
        if (kk <= 64) {
            for (int a = 0; a < kk; ++a)
                if (!((sup >> a) & 1ull)) sup |= smask[bb0 + a];
        } else {
            // robust serial fallback (practically never taken): flags in smask
            for (int a = 0; a < kk; ++a) smask[bb0 + a] = 0ull;
            for (int a = 0; a < kk; ++a) {
                if (smask[bb0 + a]) continue;
                float X1 = ss1[bb0 + a], X2 = ss2[bb0 + a], W = ssw[bb0 + a];
                for (int qq = a + 1; qq < kk; ++qq) {
                    float inter = fmaxf(0.0f, fminf(X2, ss2[bb0 + qq])
                                            - fmaxf(X1, ss1[bb0 + qq]));
                    float uni   = W + ssw[bb0 + qq] - inter;
                    if (inter / fmaxf(uni, 1e-9f) > 0.5f) smask[bb0 + qq] = 1ull;
                }
            }
        }
        gsup[tid] = sup;
    }
    __syncthreads();

    // ---- output keep mask ----
    if (tid < NN) {
        bool suppressed = (k <= 64) ? (((gsup[g] >> r) & 1ull) != 0ull)
                                    : (smask[base0 + r] != 0ull);
        out[OFF_KEEP + (size_t)b * NN + tid] = suppressed ? 0.0f : 1.0f;
    }

    // ---- spin-wait for g_keep (latency hidden behind the NMS tail) ----
    if (tid == 0) {
        volatile unsigned* pa = &g_arrive;
        while (*pa < (unsigned)BB) __nanosleep(40);
        __threadfence();
    }
    __syncthreads();

    // ---- box update (needs batch-0 keep mask) ----
    if (tid < NN) {
        const size_t idx = (size_t)b * NN + tid;
        const int kp = __ldcg(&g_keep_arr[tid]);
        float pn0 = (sqrt_recip * bt.x - bs.x) / sqrt_recipm1;
        float pn1 = (sqrt_recip * bt.y - bs.y) / sqrt_recipm1;
        float2 u;
        u.x = kp ? bs.x * sq_an + ccoef * pn0 + sigma * nz.x : fz.x;
        u.y = kp ? bs.y * sq_an + ccoef * pn1 + sigma * nz.y : fz.y;
        ((float2*)out)[idx] = u;
    }

    // ---- depart: last block resets counters (replay-safe) ----
    if (tid == 0) {
        unsigned d = atomicAdd(&g_depart, 1u);
        if (d == (unsigned)(BB - 1)) { g_arrive = 0u; g_depart = 0u; }
    }
}

// ---------------------------------------------------------------------------
// Inputs (metadata order):
//  0 boxes_t          (128,500,2)    f32
//  1 predicted_class  (6,128,500,80) f32
//  2 predicted_boxes  (6,128,500,2)  f32
//  3 noise            (128,500,2)    f32
//  4 fresh_noise      (128,500,2)    f32
//  5 alphas_cumprod   (1000,)        f32
//  6 t_now            scalar         i32
//  7 t_next           scalar         i32
// ---------------------------------------------------------------------------
extern "C" void kernel_launch(void* const* d_in, const int* in_sizes, int n_in,
                              void* d_out, int out_size)
{
    const float* boxes_t = (const float*)d_in[0];
    const float* pc      = (const float*)d_in[1];
    const float* pb      = (const float*)d_in[2];
    const float* noise   = (const float*)d_in[3];
    const float* fresh   = (const float*)d_in[4];
    const float* ac      = (const float*)d_in[5];
    const int*   t_now   = (const int*)d_in[6];
    const int*   t_next  = (const int*)d_in[7];
    float* out = (float*)d_out;

    fused_kernel<<<BB, 1024>>>(boxes_t, pc, pb, noise, fresh, ac, t_now, t_next, out);
}